// round 9
// baseline (speedup 1.0000x reference)
#include <cuda_runtime.h>
#include <cstdint>

// ---------------- problem constants ----------------
#define TSEQ   4096
#define EMB    300
#define HID    500
#define HP     512            // padded hidden (pad 500..511 never written -> stays 0)
#define GATES  2000           // 4*HID, torch gate order i,f,g,o
#define NCLS   90

// ---------------- persistent-kernel config ----------------
// 126 CTAs x 384 threads (12 warps), 1 unit per warp, 64 weight regs per lane.
//   CTAs [0,42):   layer-0 recurrence  (units via W_hh0, xp0 precomputed)
//   CTAs [42,84):  helpers: xp1 = W_ih1 @ h1[t+1] + biases (pipeline stage, no self-loop)
//   CTAs [84,126): layer-1 recurrence  (units via W_hh1, xp1 from helpers)
#define NBC    42             // CTAs per role
#define NW     12             // warps per CTA
#define THREADS 384
#define NBLK   (3 * NBC)      // 126 <= 148 -> all co-resident at occupancy 1

#define NGRP   8
// 42 producers = 2*6 + 6*5
__device__ __forceinline__ int quota42(int g) { return (g < 2) ? 6 : 5; }

#define XP1S   2048           // xp1 row stride: unit*4+gate, 504*4=2016 padded

// ---------------- device scratch (static allocation only) ----------------
__device__ float g_xp0[(size_t)TSEQ * GATES];        // layer-0 input projection (precomputed)
__device__ float g_xp1[(size_t)(TSEQ + 1) * XP1S];   // layer-1 input projection (pipelined)
__device__ float g_h1[(TSEQ + 1) * HP];              // layer-0 hidden (row 0 = zeros)
__device__ float g_h2[(TSEQ + 1) * HP];              // layer-1 hidden (row 0 = zeros)
__device__ int   g_c1[(TSEQ + 1) * NGRP];            // h1 row-ready (42 producers)
__device__ int   g_c2[(TSEQ + 1) * NGRP];            // h2 row-ready (42 producers)
__device__ int   g_c3[(TSEQ + 1) * NGRP];            // xp1 row-ready (42 producers)
__device__ float g_Wt[EMB * GATES];                  // W_ih0 transposed

// ---------------- acquire/release primitives ----------------
__device__ __forceinline__ int ld_acq(const int* p) {
    int v;
    asm volatile("ld.acquire.gpu.global.b32 %0, [%1];" : "=r"(v) : "l"(p) : "memory");
    return v;
}
__device__ __forceinline__ void red_release(int* p) {
    asm volatile("red.release.gpu.global.add.u32 [%0], 1;" :: "l"(p) : "memory");
}

// ---------------- init: reset counters every replay ----------------
__global__ void k_init() {
    const int n = (TSEQ + 1) * NGRP;
    for (int i = blockIdx.x * blockDim.x + threadIdx.x; i < 3 * n;
         i += gridDim.x * blockDim.x) {
        int which = i / n, j = i % n;
        int v = (j < NGRP) ? quota42(j & 7) : 0;     // row 0 = ready
        if (which == 0) g_c1[j] = v;
        else if (which == 1) g_c2[j] = v;
        else g_c3[j] = v;
    }
}

// ---------------- transpose W_ih0 [2000,300] -> [300,2000] ----------------
__global__ void k_transpose(const float* __restrict__ W) {
    int idx = blockIdx.x * 256 + threadIdx.x;
    if (idx < EMB * GATES) {
        int e = idx / GATES;
        int g = idx % GATES;
        g_Wt[idx] = W[g * EMB + e];
    }
}

// ---------------- x-projection GEMM for layer 0 (time-parallel, precomputed) ----------
__global__ void k_xproj(const int* __restrict__ seq,
                        const float* __restrict__ emb,
                        const float* __restrict__ bih0,
                        const float* __restrict__ bhh0) {
    __shared__ __align__(16) float embs[16][304];
    int g  = blockIdx.x * 128 + threadIdx.x;
    int t0 = blockIdx.y * 16;

    for (int idx = threadIdx.x; idx < 16 * 304; idx += 128) {
        int tt = idx / 304, e = idx % 304;
        float v = 0.f;
        if (e < EMB) v = emb[(size_t)seq[t0 + tt] * EMB + e];
        embs[tt][e] = v;
    }
    __syncthreads();

    float acc[16];
    float b = (g < GATES) ? (bih0[g] + bhh0[g]) : 0.f;
#pragma unroll
    for (int tt = 0; tt < 16; tt++) acc[tt] = b;

    for (int e4 = 0; e4 < 75; e4++) {
        float w0 = 0.f, w1 = 0.f, w2 = 0.f, w3 = 0.f;
        if (g < GATES) {
            w0 = g_Wt[(e4 * 4 + 0) * GATES + g];
            w1 = g_Wt[(e4 * 4 + 1) * GATES + g];
            w2 = g_Wt[(e4 * 4 + 2) * GATES + g];
            w3 = g_Wt[(e4 * 4 + 3) * GATES + g];
        }
#pragma unroll
        for (int tt = 0; tt < 16; tt++) {
            float4 ev = *reinterpret_cast<const float4*>(&embs[tt][e4 * 4]);
            acc[tt] = fmaf(ev.x, w0, fmaf(ev.y, w1, fmaf(ev.z, w2, fmaf(ev.w, w3, acc[tt]))));
        }
    }
    if (g < GATES) {
#pragma unroll
        for (int tt = 0; tt < 16; tt++)
            g_xp0[(size_t)(t0 + tt) * GATES + g] = acc[tt];
    }
}

__device__ __forceinline__ float sigf(float x)     { return 1.f / (1.f + __expf(-x)); }
__device__ __forceinline__ float tanhfast(float x) { return 1.f - 2.f / (__expf(2.f * x) + 1.f); }

// butterfly-reduce 4 accumulators; afterwards ALL lanes hold all 4 full sums
__device__ __forceinline__ void reduce4(float (&a)[4]) {
#pragma unroll
    for (int off = 16; off; off >>= 1) {
#pragma unroll
        for (int j = 0; j < 4; j++)
            a[j] += __shfl_xor_sync(0xffffffffu, a[j], off);
    }
}

// grouped-counter poll, lanes 0-7 watch the 8 group words of one row
__device__ __forceinline__ void poll_row(const int* row, int l) {
    const int* cp = row + (l & 7);
    const int need = quota42(l & 7);
    for (;;) {
        int v = (l < NGRP) ? ld_acq(cp) : need;
        if (__all_sync(0xffffffffu, v >= need)) break;
    }
}

// ---------------- persistent warp-per-unit LSTM ----------------
__global__ __launch_bounds__(THREADS, 1)
void k_lstm(const float* __restrict__ Whh0,
            const float* __restrict__ Wih1,
            const float* __restrict__ Whh1,
            const float* __restrict__ bih1,
            const float* __restrict__ bhh1) {
    const int b   = blockIdx.x;
    const int tid = threadIdx.x;
    const int w = tid >> 5, l = tid & 31;

    float wreg[4][16];

    if (b < NBC) {
        // ============ LAYER 0: one warp = one unit (4 gate rows) ============
        const int u = b * NW + w;            // 0..503
        const bool live = (u < HID);
        const int grp = b & 7;
#pragma unroll
        for (int q = 0; q < 4; q++) {
            const float* Wr = Whh0 + (size_t)(q * HID + (live ? u : 0)) * HID;
#pragma unroll
            for (int k = 0; k < 16; k++) {
                int idx = l + 32 * k;
                wreg[q][k] = (live && idx < HID) ? Wr[idx] : 0.f;
            }
        }
        float c = 0.f;

        for (int t = 0; t < TSEQ; t++) {
            // lane 0 prefetches xp0 (independent; hides under poll)
            float xpi = 0.f, xpf = 0.f, xpg = 0.f, xpo = 0.f;
            if (l == 0 && live) {
                const float* xp = &g_xp0[(size_t)t * GATES + u];
                xpi = __ldcg(xp + 0 * HID);
                xpf = __ldcg(xp + 1 * HID);
                xpg = __ldcg(xp + 2 * HID);
                xpo = __ldcg(xp + 3 * HID);
            }
            poll_row(&g_c1[t * NGRP], l);

            const float* hr = &g_h1[(size_t)t * HP];
            float x[16];
#pragma unroll
            for (int k = 0; k < 16; k++) x[k] = __ldcg(hr + l + 32 * k);

            float acc[4];
#pragma unroll
            for (int q = 0; q < 4; q++) {
                float a = 0.f;
#pragma unroll
                for (int k = 0; k < 16; k++) a = fmaf(wreg[q][k], x[k], a);
                acc[q] = a;
            }
            reduce4(acc);

            if (l == 0 && live) {
                float ig = sigf(acc[0] + xpi);
                float fg = sigf(acc[1] + xpf);
                float gg = tanhfast(acc[2] + xpg);
                float og = sigf(acc[3] + xpo);
                c = fg * c + ig * gg;
                __stcg(&g_h1[(size_t)(t + 1) * HP + u], og * tanhfast(c));
            }
            __syncthreads();                   // all 12 units of this CTA stored
            if (tid == 0) {
                __threadfence();               // grid.sync-style release of peers' stores
                red_release(&g_c1[(t + 1) * NGRP + grp]);
            }
        }
    } else if (b < 2 * NBC) {
        // ============ HELPERS: xp1[t+1] = W_ih1 @ h1[t+1] + biases ============
        const int u = (b - NBC) * NW + w;      // 0..503
        const bool live = (u < HID);
        const int grp = (b - NBC) & 7;
#pragma unroll
        for (int q = 0; q < 4; q++) {
            const float* Wr = Wih1 + (size_t)(q * HID + (live ? u : 0)) * HID;
#pragma unroll
            for (int k = 0; k < 16; k++) {
                int idx = l + 32 * k;
                wreg[q][k] = (live && idx < HID) ? Wr[idx] : 0.f;
            }
        }
        float bi = 0.f, bf = 0.f, bg = 0.f, bo = 0.f;
        if (l == 0 && live) {
            bi = bih1[0 * HID + u] + bhh1[0 * HID + u];
            bf = bih1[1 * HID + u] + bhh1[1 * HID + u];
            bg = bih1[2 * HID + u] + bhh1[2 * HID + u];
            bo = bih1[3 * HID + u] + bhh1[3 * HID + u];
        }

        for (int t = 0; t < TSEQ; t++) {
            poll_row(&g_c1[(t + 1) * NGRP], l);

            const float* hr = &g_h1[(size_t)(t + 1) * HP];
            float x[16];
#pragma unroll
            for (int k = 0; k < 16; k++) x[k] = __ldcg(hr + l + 32 * k);

            float acc[4];
#pragma unroll
            for (int q = 0; q < 4; q++) {
                float a = 0.f;
#pragma unroll
                for (int k = 0; k < 16; k++) a = fmaf(wreg[q][k], x[k], a);
                acc[q] = a;
            }
            reduce4(acc);

            if (l == 0) {
                float4 o = make_float4(acc[0] + bi, acc[1] + bf,
                                       acc[2] + bg, acc[3] + bo);
                asm volatile("st.global.cg.v4.f32 [%0], {%1,%2,%3,%4};"
                             :: "l"(&g_xp1[(size_t)(t + 1) * XP1S + u * 4]),
                                "f"(o.x), "f"(o.y), "f"(o.z), "f"(o.w) : "memory");
            }
            __syncthreads();
            if (tid == 0) {
                __threadfence();
                red_release(&g_c3[(t + 1) * NGRP + grp]);
            }
        }
    } else {
        // ============ LAYER 1: one warp = one unit (4 hh rows) ============
        const int u = (b - 2 * NBC) * NW + w;  // 0..503
        const bool live = (u < HID);
        const int grp = (b - 2 * NBC) & 7;
#pragma unroll
        for (int q = 0; q < 4; q++) {
            const float* Wr = Whh1 + (size_t)(q * HID + (live ? u : 0)) * HID;
#pragma unroll
            for (int k = 0; k < 16; k++) {
                int idx = l + 32 * k;
                wreg[q][k] = (live && idx < HID) ? Wr[idx] : 0.f;
            }
        }
        float c = 0.f;

        for (int t = 0; t < TSEQ; t++) {
            // combined poll: lanes 0-7 watch xp1[t+1], lanes 8-15 watch h2[t]
            {
                const int* cp3 = &g_c3[(t + 1) * NGRP + (l & 7)];
                const int* cp2 = &g_c2[t * NGRP + (l & 7)];
                const int need = quota42(l & 7);
                for (;;) {
                    int v = (l < NGRP) ? ld_acq(cp3)
                          : (l < 2 * NGRP) ? ld_acq(cp2) : need;
                    if (__all_sync(0xffffffffu, v >= need)) break;
                }
            }
            // xp1 fetch + h2 row fetch overlap in one round trip
            float4 xp = make_float4(0.f, 0.f, 0.f, 0.f);
            if (l == 0 && live)
                xp = *reinterpret_cast<const float4*>(
                        &g_xp1[(size_t)(t + 1) * XP1S + u * 4]);

            const float* hr = &g_h2[(size_t)t * HP];
            float x[16];
#pragma unroll
            for (int k = 0; k < 16; k++) x[k] = __ldcg(hr + l + 32 * k);

            float acc[4];
#pragma unroll
            for (int q = 0; q < 4; q++) {
                float a = 0.f;
#pragma unroll
                for (int k = 0; k < 16; k++) a = fmaf(wreg[q][k], x[k], a);
                acc[q] = a;
            }
            reduce4(acc);

            if (l == 0 && live) {
                float ig = sigf(acc[0] + xp.x);
                float fg = sigf(acc[1] + xp.y);
                float gg = tanhfast(acc[2] + xp.z);
                float og = sigf(acc[3] + xp.w);
                c = fg * c + ig * gg;
                __stcg(&g_h2[(size_t)(t + 1) * HP + u], og * tanhfast(c));
            }
            __syncthreads();
            if (tid == 0) {
                __threadfence();
                red_release(&g_c2[(t + 1) * NGRP + grp]);
            }
        }
    }
}

// ---------------- final FC: out = h2[last] @ fc_W^T + fc_b ----------------
__global__ void k_fc(const float* __restrict__ fcW,
                     const float* __restrict__ fcb,
                     float* __restrict__ out) {
    int b = blockIdx.x;
    int l = threadIdx.x;
    float acc = 0.f;
    for (int k = l; k < HID; k += 32)
        acc += fcW[b * HID + k] * g_h2[TSEQ * HP + k];
#pragma unroll
    for (int off = 16; off; off >>= 1)
        acc += __shfl_xor_sync(0xffffffffu, acc, off);
    if (l == 0) out[b] = acc + fcb[b];
}

// ---------------- launch ----------------
extern "C" void kernel_launch(void* const* d_in, const int* in_sizes, int n_in,
                              void* d_out, int out_size) {
    const int*   seq  = (const int*)  d_in[0];
    const float* emb  = (const float*)d_in[1];
    const float* Wih0 = (const float*)d_in[2];
    const float* Whh0 = (const float*)d_in[3];
    const float* bih0 = (const float*)d_in[4];
    const float* bhh0 = (const float*)d_in[5];
    const float* Wih1 = (const float*)d_in[6];
    const float* Whh1 = (const float*)d_in[7];
    const float* bih1 = (const float*)d_in[8];
    const float* bhh1 = (const float*)d_in[9];
    const float* fcW  = (const float*)d_in[10];
    const float* fcb  = (const float*)d_in[11];

    k_init<<<64, 256>>>();
    k_transpose<<<(EMB * GATES + 255) / 256, 256>>>(Wih0);
    dim3 gx(16, 256);
    k_xproj<<<gx, 128>>>(seq, emb, bih0, bhh0);
    k_lstm<<<NBLK, THREADS>>>(Whh0, Wih1, Whh1, bih1, bhh1);
    k_fc<<<NCLS, 32>>>(fcW, fcb, (float*)d_out);
}

// round 10
// speedup vs baseline: 1.5390x; 1.5390x over previous
#include <cuda_runtime.h>
#include <cstdint>

// ---------------- problem constants ----------------
#define TSEQ   4096
#define EMB    300
#define HID    500
#define HP     512            // padded hidden (pad 500..511 = 0.0 always, never NaN)
#define GATES  2000           // 4*HID, torch gate order i,f,g,o
#define NCLS   90

// ---------------- persistent-kernel config (R6 champion topology, unchanged) ----------------
#define NB0    50             // layer-0 CTAs, 10 units each
#define U0     10
#define RPW0   5              // 40 rows / 8 warps
#define NB1    84             // layer-1 CTAs, 6 units each
#define U1     6
#define RPW1   6              // 48 half-rows / 8 warps
#define NBLK   (NB0 + NB1)    // 134 <= 148
#define THREADS 256

#define NGRP   8
__device__ __forceinline__ int quota1(int g) { return (g < 2) ? 7 : 6; }    // 50 producers
__device__ __forceinline__ int quota2(int g) { return (g < 4) ? 11 : 10; }  // 84 producers

// ---------------- device scratch ----------------
__device__ float g_xp0[(size_t)TSEQ * GATES];
__device__ float g_h1[(TSEQ + 1) * HP];             // row 0 = zeros (static, never rewritten)
__device__ float g_h2[(TSEQ + 1) * HP];
__device__ int   g_c1[(TSEQ + 1) * NGRP];
__device__ int   g_c2[(TSEQ + 1) * NGRP];
__device__ float g_Wt[EMB * GATES];

// ---------------- primitives ----------------
__device__ __forceinline__ int ld_acq(const int* p) {
    int v;
    asm volatile("ld.acquire.gpu.global.b32 %0, [%1];" : "=r"(v) : "l"(p) : "memory");
    return v;
}
__device__ __forceinline__ void red_release(int* p) {
    asm volatile("red.release.gpu.global.add.u32 [%0], 1;" :: "l"(p) : "memory");
}
__device__ __forceinline__ unsigned long long packf2(float a, float b) {
    unsigned long long r;
    asm("mov.b64 %0, {%1, %2};" : "=l"(r) : "f"(a), "f"(b));
    return r;
}
__device__ __forceinline__ void unpackf2(unsigned long long v, float& a, float& b) {
    asm("mov.b64 {%0, %1}, %2;" : "=f"(a), "=f"(b) : "l"(v));
}
__device__ __forceinline__ void fma2(unsigned long long& d, unsigned long long a,
                                     unsigned long long b) {
    asm("fma.rn.f32x2 %0, %1, %2, %0;" : "+l"(d) : "l"(a), "l"(b));
}

// ---------------- init: counters + NaN-sentinel h rows (every replay) ----------------
__global__ void k_init() {
    const int n = (TSEQ + 1) * NGRP;
    for (int i = blockIdx.x * blockDim.x + threadIdx.x; i < 2 * n;
         i += gridDim.x * blockDim.x) {
        if (i < n) g_c1[i] = (i < NGRP) ? quota1(i & 7) : 0;
        else { int j = i - n; g_c2[j] = (j < NGRP) ? quota2(j & 7) : 0; }
    }
    // NaN-fill h1/h2 rows 1..TSEQ: cols<500 NaN, cols 500..511 = 0.0
    const size_t nvec = (size_t)TSEQ * (HP / 4);
    const uint4 nanv  = make_uint4(0x7FC00000u, 0x7FC00000u, 0x7FC00000u, 0x7FC00000u);
    const uint4 zerov = make_uint4(0u, 0u, 0u, 0u);
    uint4* a = reinterpret_cast<uint4*>(g_h1 + HP);
    uint4* b = reinterpret_cast<uint4*>(g_h2 + HP);
    for (size_t i = blockIdx.x * blockDim.x + threadIdx.x; i < 2 * nvec;
         i += (size_t)gridDim.x * blockDim.x) {
        size_t j = (i < nvec) ? i : i - nvec;
        int col4 = (int)(j & (HP / 4 - 1));
        uint4 v = (col4 < 125) ? nanv : zerov;     // 125*4 = 500
        if (i < nvec) a[j] = v; else b[j] = v;
    }
}

// ---------------- transpose W_ih0 ----------------
__global__ void k_transpose(const float* __restrict__ W) {
    int idx = blockIdx.x * 256 + threadIdx.x;
    if (idx < EMB * GATES) {
        int e = idx / GATES;
        int g = idx % GATES;
        g_Wt[idx] = W[g * EMB + e];
    }
}

// ---------------- x-projection GEMM (unchanged) ----------------
__global__ void k_xproj(const int* __restrict__ seq,
                        const float* __restrict__ emb,
                        const float* __restrict__ bih0,
                        const float* __restrict__ bhh0) {
    __shared__ __align__(16) float embs[16][304];
    int g  = blockIdx.x * 128 + threadIdx.x;
    int t0 = blockIdx.y * 16;

    for (int idx = threadIdx.x; idx < 16 * 304; idx += 128) {
        int tt = idx / 304, e = idx % 304;
        float v = 0.f;
        if (e < EMB) v = emb[(size_t)seq[t0 + tt] * EMB + e];
        embs[tt][e] = v;
    }
    __syncthreads();

    float acc[16];
    float b = (g < GATES) ? (bih0[g] + bhh0[g]) : 0.f;
#pragma unroll
    for (int tt = 0; tt < 16; tt++) acc[tt] = b;

    for (int e4 = 0; e4 < 75; e4++) {
        float w0 = 0.f, w1 = 0.f, w2 = 0.f, w3 = 0.f;
        if (g < GATES) {
            w0 = g_Wt[(e4 * 4 + 0) * GATES + g];
            w1 = g_Wt[(e4 * 4 + 1) * GATES + g];
            w2 = g_Wt[(e4 * 4 + 2) * GATES + g];
            w3 = g_Wt[(e4 * 4 + 3) * GATES + g];
        }
#pragma unroll
        for (int tt = 0; tt < 16; tt++) {
            float4 ev = *reinterpret_cast<const float4*>(&embs[tt][e4 * 4]);
            acc[tt] = fmaf(ev.x, w0, fmaf(ev.y, w1, fmaf(ev.z, w2, fmaf(ev.w, w3, acc[tt]))));
        }
    }
    if (g < GATES) {
#pragma unroll
        for (int tt = 0; tt < 16; tt++)
            g_xp0[(size_t)(t0 + tt) * GATES + g] = acc[tt];
    }
}

__device__ __forceinline__ float sigf(float x)     { return 1.f / (1.f + __expf(-x)); }
__device__ __forceinline__ float tanhfast(float x) { return 1.f - 2.f / (__expf(2.f * x) + 1.f); }

__device__ __forceinline__ void load16(const float* __restrict__ hr, int l, float (&x)[16]) {
#pragma unroll
    for (int k = 0; k < 16; k++) x[k] = __ldcg(hr + l + 32 * k);
}
// one acquire probe of a counter row; need is per-lane
__device__ __forceinline__ bool probe(const int* crow, int l, int need) {
    int v = (l < NGRP) ? ld_acq(crow + (l & 7)) : need;
    return __all_sync(0xffffffffu, v >= need);
}
// speculative load + overlapped probe; fallback = counter spin + one reload
__device__ __forceinline__ void acquire_row(const float* __restrict__ hr,
                                            const int* crow, int l, int need,
                                            float (&x)[16]) {
    load16(hr, l, x);                          // speculative (in flight with probe)
    bool ok = false;
    if (probe(crow, l, need)) {
        float s = 0.f;
#pragma unroll
        for (int k = 0; k < 16; k++) s += x[k];
        ok = (__ballot_sync(0xffffffffu, s != s) == 0u);
    }
    if (!ok) {
        while (!probe(crow, l, need)) {}
        load16(hr, l, x);                      // counter-ordered, valid
    }
}

// ---------------- persistent 2-layer LSTM recurrence (R6 + FMA2 + overlap) ----------------
__global__ __launch_bounds__(THREADS, 1)
void k_lstm(const float* __restrict__ Whh0,
            const float* __restrict__ Wih1,
            const float* __restrict__ Whh1,
            const float* __restrict__ bih1,
            const float* __restrict__ bhh1) {
    int b   = blockIdx.x;
    int tid = threadIdx.x;
    int w = tid >> 5, l = tid & 31;

    __shared__ float sums[2][48];
    unsigned long long w2[6][8];               // packed f32x2 weights

    if (b < NB0) {
        // ======================= LAYER 0 =======================
        const int ub = b * U0;
        const int grp = b & 7;
#pragma unroll
        for (int j = 0; j < RPW0; j++) {
            int r = w * RPW0 + j;
            int q = r / U0, u = r % U0;
            const float* Wr = Whh0 + (size_t)(q * HID + ub + u) * HID;
#pragma unroll
            for (int p = 0; p < 8; p++) {
                int ia = l + 32 * (2 * p), ib = l + 32 * (2 * p + 1);
                float wa = (ia < HID) ? Wr[ia] : 0.f;
                float wb = (ib < HID) ? Wr[ib] : 0.f;
                w2[j][p] = packf2(wa, wb);
            }
        }
        float c = 0.f;
        const int need = quota1(l & 7);

        for (int t = 0; t < TSEQ; t++) {
            float xp0v = 0.f, xp1v = 0.f, xp2v = 0.f, xp3v = 0.f;
            if (tid < U0) {
                const float* xp = &g_xp0[(size_t)t * GATES + ub + tid];
                xp0v = __ldcg(xp + 0 * HID);
                xp1v = __ldcg(xp + 1 * HID);
                xp2v = __ldcg(xp + 2 * HID);
                xp3v = __ldcg(xp + 3 * HID);
            }

            float x[16];
            acquire_row(&g_h1[(size_t)t * HP], &g_c1[t * NGRP], l, need, x);
            unsigned long long x2[8];
#pragma unroll
            for (int p = 0; p < 8; p++) x2[p] = packf2(x[2 * p], x[2 * p + 1]);

            float* sb = sums[t & 1];
#pragma unroll
            for (int j = 0; j < RPW0; j++) {
                unsigned long long a2 = 0ULL;
#pragma unroll
                for (int p = 0; p < 8; p++) fma2(a2, w2[j][p], x2[p]);
                float lo, hi; unpackf2(a2, lo, hi);
                float acc = lo + hi;
#pragma unroll
                for (int off = 16; off; off >>= 1)
                    acc += __shfl_xor_sync(0xffffffffu, acc, off);
                if (l == 0) sb[w * RPW0 + j] = acc;
            }
            __syncthreads();

            if (w == 0) {
                if (l < U0) {
                    float pi = sb[0 * U0 + l] + xp0v;
                    float pf = sb[1 * U0 + l] + xp1v;
                    float pg = sb[2 * U0 + l] + xp2v;
                    float po = sb[3 * U0 + l] + xp3v;
                    float ig = sigf(pi), fg = sigf(pf), og = sigf(po);
                    float gg = tanhfast(pg);
                    c = fg * c + ig * gg;
                    __stcg(&g_h1[(size_t)(t + 1) * HP + ub + l], og * tanhfast(c));
                }
                __syncwarp();
                if (l == 0) red_release(&g_c1[(t + 1) * NGRP + grp]);
            }
        }
    } else {
        // ======================= LAYER 1 =======================
        const int bb = b - NB0;
        const int ub = bb * U1;
        const int grp = bb & 7;
#pragma unroll
        for (int j = 0; j < RPW1; j++) {
            int hr = w * RPW1 + j;             // [0,24)=W_ih1 (x=h1), [24,48)=W_hh1 (x=h2)
            int rl = hr % 24;
            int q = rl / U1, u = rl % U1;
            int ug = ub + u;
            const float* W = (hr >= 24) ? Whh1 : Wih1;
            const float* Wr = W + (size_t)(q * HID + (ug < HID ? ug : 0)) * HID;
#pragma unroll
            for (int p = 0; p < 8; p++) {
                int ia = l + 32 * (2 * p), ib = l + 32 * (2 * p + 1);
                float wa = (ug < HID && ia < HID) ? Wr[ia] : 0.f;
                float wb = (ug < HID && ib < HID) ? Wr[ib] : 0.f;
                w2[j][p] = packf2(wa, wb);
            }
        }
        float bg0 = 0.f, bg1 = 0.f, bg2 = 0.f, bg3 = 0.f, c = 0.f;
        if (tid < U1 && (ub + tid) < HID) {
            int base = ub + tid;
            bg0 = bih1[0 * HID + base] + bhh1[0 * HID + base];
            bg1 = bih1[1 * HID + base] + bhh1[1 * HID + base];
            bg2 = bih1[2 * HID + base] + bhh1[2 * HID + base];
            bg3 = bih1[3 * HID + base] + bhh1[3 * HID + base];
        }
        // each warp waits ONLY on its own source
        const int need = (w < 4) ? quota1(l & 7) : quota2(l & 7);

        for (int t = 0; t < TSEQ; t++) {
            const float* xs;
            const int*   cr;
            if (w < 4) { xs = &g_h1[(size_t)(t + 1) * HP]; cr = &g_c1[(t + 1) * NGRP]; }
            else       { xs = &g_h2[(size_t)t * HP];       cr = &g_c2[t * NGRP]; }

            float x[16];
            acquire_row(xs, cr, l, need, x);
            unsigned long long x2[8];
#pragma unroll
            for (int p = 0; p < 8; p++) x2[p] = packf2(x[2 * p], x[2 * p + 1]);

            float* sb = sums[t & 1];
#pragma unroll
            for (int j = 0; j < RPW1; j++) {
                unsigned long long a2 = 0ULL;
#pragma unroll
                for (int p = 0; p < 8; p++) fma2(a2, w2[j][p], x2[p]);
                float lo, hi; unpackf2(a2, lo, hi);
                float acc = lo + hi;
#pragma unroll
                for (int off = 16; off; off >>= 1)
                    acc += __shfl_xor_sync(0xffffffffu, acc, off);
                if (l == 0) sb[w * RPW1 + j] = acc;
            }
            __syncthreads();

            if (w == 0) {
                if (l < U1) {
                    float pi = sb[0 * U1 + l] + sb[24 + 0 * U1 + l] + bg0;
                    float pf = sb[1 * U1 + l] + sb[24 + 1 * U1 + l] + bg1;
                    float pg = sb[2 * U1 + l] + sb[24 + 2 * U1 + l] + bg2;
                    float po = sb[3 * U1 + l] + sb[24 + 3 * U1 + l] + bg3;
                    float ig = sigf(pi), fg = sigf(pf), og = sigf(po);
                    float gg = tanhfast(pg);
                    c = fg * c + ig * gg;
                    if ((ub + l) < HID)
                        __stcg(&g_h2[(size_t)(t + 1) * HP + ub + l], og * tanhfast(c));
                }
                __syncwarp();
                if (l == 0) red_release(&g_c2[(t + 1) * NGRP + grp]);
            }
        }
    }
}

// ---------------- final FC ----------------
__global__ void k_fc(const float* __restrict__ fcW,
                     const float* __restrict__ fcb,
                     float* __restrict__ out) {
    int b = blockIdx.x;
    int l = threadIdx.x;
    float acc = 0.f;
    for (int k = l; k < HID; k += 32)
        acc += fcW[b * HID + k] * g_h2[TSEQ * HP + k];
#pragma unroll
    for (int off = 16; off; off >>= 1)
        acc += __shfl_xor_sync(0xffffffffu, acc, off);
    if (l == 0) out[b] = acc + fcb[b];
}

// ---------------- launch ----------------
extern "C" void kernel_launch(void* const* d_in, const int* in_sizes, int n_in,
                              void* d_out, int out_size) {
    const int*   seq  = (const int*)  d_in[0];
    const float* emb  = (const float*)d_in[1];
    const float* Wih0 = (const float*)d_in[2];
    const float* Whh0 = (const float*)d_in[3];
    const float* bih0 = (const float*)d_in[4];
    const float* bhh0 = (const float*)d_in[5];
    const float* Wih1 = (const float*)d_in[6];
    const float* Whh1 = (const float*)d_in[7];
    const float* bih1 = (const float*)d_in[8];
    const float* bhh1 = (const float*)d_in[9];
    const float* fcW  = (const float*)d_in[10];
    const float* fcb  = (const float*)d_in[11];

    k_init<<<148, 256>>>();
    k_transpose<<<(EMB * GATES + 255) / 256, 256>>>(Wih0);
    dim3 gx(16, 256);
    k_xproj<<<gx, 128>>>(seq, emb, bih0, bhh0);
    k_lstm<<<NBLK, THREADS>>>(Whh0, Wih1, Whh1, bih1, bhh1);
    k_fc<<<NCLS, 32>>>(fcW, fcb, (float*)d_out);
}

// round 11
// speedup vs baseline: 1.6740x; 1.0877x over previous
#include <cuda_runtime.h>
#include <cstdint>

// ---------------- problem constants ----------------
#define TSEQ   4096
#define EMB    300
#define HID    500
#define HP     512            // padded hidden (pad 500..511 = 0.0 always, never NaN)
#define GATES  2000           // 4*HID, torch gate order i,f,g,o
#define NCLS   90

// ---------------- persistent-kernel config (R6 champion topology, unchanged) ----------------
#define NB0    50             // layer-0 CTAs, 10 units each
#define U0     10
#define RPW0   5              // 40 rows / 8 warps
#define NB1    84             // layer-1 CTAs, 6 units each
#define U1     6
#define RPW1   6              // 48 half-rows / 8 warps
#define NBLK   (NB0 + NB1)    // 134 <= 148
#define THREADS 256

#define NGRP   8
__device__ __forceinline__ int quota1(int g) { return (g < 2) ? 7 : 6; }    // 50 producers
__device__ __forceinline__ int quota2(int g) { return (g < 4) ? 11 : 10; }  // 84 producers

// ---------------- device scratch ----------------
__device__ float g_xp0[(size_t)TSEQ * GATES];
__device__ float g_h1[(TSEQ + 1) * HP];             // row 0 = zeros (static, never rewritten)
__device__ float g_h2[(TSEQ + 1) * HP];
__device__ int   g_c1[(TSEQ + 1) * NGRP];
__device__ int   g_c2[(TSEQ + 1) * NGRP];
__device__ float g_Wt[EMB * GATES];

// ---------------- primitives ----------------
__device__ __forceinline__ int ld_acq(const int* p) {
    int v;
    asm volatile("ld.acquire.gpu.global.b32 %0, [%1];" : "=r"(v) : "l"(p) : "memory");
    return v;
}
__device__ __forceinline__ void red_release(int* p) {
    asm volatile("red.release.gpu.global.add.u32 [%0], 1;" :: "l"(p) : "memory");
}

// ---------------- init: counters + NaN-sentinel h rows (every replay) ----------------
__global__ void k_init() {
    const int n = (TSEQ + 1) * NGRP;
    for (int i = blockIdx.x * blockDim.x + threadIdx.x; i < 2 * n;
         i += gridDim.x * blockDim.x) {
        if (i < n) g_c1[i] = (i < NGRP) ? quota1(i & 7) : 0;
        else { int j = i - n; g_c2[j] = (j < NGRP) ? quota2(j & 7) : 0; }
    }
    // NaN-fill h1/h2 rows 1..TSEQ: cols<500 NaN, cols 500..511 = 0.0
    const size_t nvec = (size_t)TSEQ * (HP / 4);
    const uint4 nanv  = make_uint4(0x7FC00000u, 0x7FC00000u, 0x7FC00000u, 0x7FC00000u);
    const uint4 zerov = make_uint4(0u, 0u, 0u, 0u);
    uint4* a = reinterpret_cast<uint4*>(g_h1 + HP);
    uint4* b = reinterpret_cast<uint4*>(g_h2 + HP);
    for (size_t i = blockIdx.x * blockDim.x + threadIdx.x; i < 2 * nvec;
         i += (size_t)gridDim.x * blockDim.x) {
        size_t j = (i < nvec) ? i : i - nvec;
        int col4 = (int)(j & (HP / 4 - 1));
        uint4 v = (col4 < 125) ? nanv : zerov;     // 125*4 = 500
        if (i < nvec) a[j] = v; else b[j] = v;
    }
}

// ---------------- transpose W_ih0 ----------------
__global__ void k_transpose(const float* __restrict__ W) {
    int idx = blockIdx.x * 256 + threadIdx.x;
    if (idx < EMB * GATES) {
        int e = idx / GATES;
        int g = idx % GATES;
        g_Wt[idx] = W[g * EMB + e];
    }
}

// ---------------- x-projection GEMM (unchanged) ----------------
__global__ void k_xproj(const int* __restrict__ seq,
                        const float* __restrict__ emb,
                        const float* __restrict__ bih0,
                        const float* __restrict__ bhh0) {
    __shared__ __align__(16) float embs[16][304];
    int g  = blockIdx.x * 128 + threadIdx.x;
    int t0 = blockIdx.y * 16;

    for (int idx = threadIdx.x; idx < 16 * 304; idx += 128) {
        int tt = idx / 304, e = idx % 304;
        float v = 0.f;
        if (e < EMB) v = emb[(size_t)seq[t0 + tt] * EMB + e];
        embs[tt][e] = v;
    }
    __syncthreads();

    float acc[16];
    float b = (g < GATES) ? (bih0[g] + bhh0[g]) : 0.f;
#pragma unroll
    for (int tt = 0; tt < 16; tt++) acc[tt] = b;

    for (int e4 = 0; e4 < 75; e4++) {
        float w0 = 0.f, w1 = 0.f, w2 = 0.f, w3 = 0.f;
        if (g < GATES) {
            w0 = g_Wt[(e4 * 4 + 0) * GATES + g];
            w1 = g_Wt[(e4 * 4 + 1) * GATES + g];
            w2 = g_Wt[(e4 * 4 + 2) * GATES + g];
            w3 = g_Wt[(e4 * 4 + 3) * GATES + g];
        }
#pragma unroll
        for (int tt = 0; tt < 16; tt++) {
            float4 ev = *reinterpret_cast<const float4*>(&embs[tt][e4 * 4]);
            acc[tt] = fmaf(ev.x, w0, fmaf(ev.y, w1, fmaf(ev.z, w2, fmaf(ev.w, w3, acc[tt]))));
        }
    }
    if (g < GATES) {
#pragma unroll
        for (int tt = 0; tt < 16; tt++)
            g_xp0[(size_t)(t0 + tt) * GATES + g] = acc[tt];
    }
}

__device__ __forceinline__ float sigf(float x)     { return 1.f / (1.f + __expf(-x)); }
__device__ __forceinline__ float tanhfast(float x) { return 1.f - 2.f / (__expf(2.f * x) + 1.f); }

__device__ __forceinline__ void load16(const float* __restrict__ hr, int l, float (&x)[16]) {
#pragma unroll
    for (int k = 0; k < 16; k++) x[k] = __ldcg(hr + l + 32 * k);
}
// one acquire probe of a counter row
__device__ __forceinline__ bool probe(const int* crow, int l, int need) {
    int v = (l < NGRP) ? ld_acq(crow + (l & 7)) : need;
    return __all_sync(0xffffffffu, v >= need);
}
// speculative x-load issued concurrently with the counter probe.
// Fast path (late consumer, counter already set): ONE L2 round trip total.
// Slow path (early consumer): counter-only spin (32B/warp/iter, no row storm),
// then one counter-ordered reload.
__device__ __forceinline__ void acquire_row(const float* __restrict__ hr,
                                            const int* crow, int l, int need,
                                            float (&x)[16]) {
    load16(hr, l, x);                          // speculative, in flight with probe
    bool ok = false;
    if (probe(crow, l, need)) {
        float s = 0.f;
#pragma unroll
        for (int k = 0; k < 16; k++) s += x[k];
        ok = (__ballot_sync(0xffffffffu, s != s) == 0u);   // NaN-free => final data
    }
    if (!ok) {
        while (!probe(crow, l, need)) {}
        load16(hr, l, x);                      // counter-ordered, guaranteed valid
    }
}

// ---------------- persistent 2-layer LSTM recurrence (R6 + overlap ONLY) ----------------
__global__ __launch_bounds__(THREADS, 1)
void k_lstm(const float* __restrict__ Whh0,
            const float* __restrict__ Wih1,
            const float* __restrict__ Whh1,
            const float* __restrict__ bih1,
            const float* __restrict__ bhh1) {
    int b   = blockIdx.x;
    int tid = threadIdx.x;
    int w = tid >> 5, l = tid & 31;

    __shared__ float sums[2][48];
    float wreg[6][16];

    if (b < NB0) {
        // ======================= LAYER 0 =======================
        const int ub = b * U0;
        const int grp = b & 7;
#pragma unroll
        for (int j = 0; j < RPW0; j++) {
            int r = w * RPW0 + j;
            int q = r / U0, u = r % U0;
            int grow = q * HID + ub + u;
#pragma unroll
            for (int k = 0; k < 16; k++) {
                int idx = l + 32 * k;
                wreg[j][k] = (idx < HID) ? Whh0[grow * HID + idx] : 0.f;
            }
        }
        float c = 0.f;
        const int need = quota1(l & 7);

        for (int t = 0; t < TSEQ; t++) {
            // xp prefetch (independent data; latency hides under wait)
            float xp0v = 0.f, xp1v = 0.f, xp2v = 0.f, xp3v = 0.f;
            if (tid < U0) {
                const float* xp = &g_xp0[(size_t)t * GATES + ub + tid];
                xp0v = __ldcg(xp + 0 * HID);
                xp1v = __ldcg(xp + 1 * HID);
                xp2v = __ldcg(xp + 2 * HID);
                xp3v = __ldcg(xp + 3 * HID);
            }

            float x[16];
            acquire_row(&g_h1[(size_t)t * HP], &g_c1[t * NGRP], l, need, x);

            float* sb = sums[t & 1];
#pragma unroll
            for (int j = 0; j < RPW0; j++) {
                float acc = 0.f;
#pragma unroll
                for (int k = 0; k < 16; k++) acc = fmaf(wreg[j][k], x[k], acc);
#pragma unroll
                for (int off = 16; off; off >>= 1)
                    acc += __shfl_xor_sync(0xffffffffu, acc, off);
                if (l == 0) sb[w * RPW0 + j] = acc;
            }
            __syncthreads();

            if (w == 0) {
                if (l < U0) {
                    float pi = sb[0 * U0 + l] + xp0v;
                    float pf = sb[1 * U0 + l] + xp1v;
                    float pg = sb[2 * U0 + l] + xp2v;
                    float po = sb[3 * U0 + l] + xp3v;
                    float ig = sigf(pi), fg = sigf(pf), og = sigf(po);
                    float gg = tanhfast(pg);
                    c = fg * c + ig * gg;
                    __stcg(&g_h1[(size_t)(t + 1) * HP + ub + l], og * tanhfast(c));
                }
                __syncwarp();
                if (l == 0) red_release(&g_c1[(t + 1) * NGRP + grp]);
            }
        }
    } else {
        // ======================= LAYER 1 =======================
        const int bb = b - NB0;
        const int ub = bb * U1;
        const int grp = bb & 7;
#pragma unroll
        for (int j = 0; j < RPW1; j++) {
            int hr = w * RPW1 + j;             // [0,24)=W_ih1 (x=h1), [24,48)=W_hh1 (x=h2)
            int rl = hr % 24;
            int q = rl / U1, u = rl % U1;
            int ug = ub + u;
            int grow = q * HID + (ug < HID ? ug : 0);
            const float* W = (hr >= 24) ? Whh1 : Wih1;
#pragma unroll
            for (int k = 0; k < 16; k++) {
                int idx = l + 32 * k;
                wreg[j][k] = (ug < HID && idx < HID) ? W[(size_t)grow * HID + idx] : 0.f;
            }
        }
        float bg0 = 0.f, bg1 = 0.f, bg2 = 0.f, bg3 = 0.f, c = 0.f;
        if (tid < U1 && (ub + tid) < HID) {
            int base = ub + tid;
            bg0 = bih1[0 * HID + base] + bhh1[0 * HID + base];
            bg1 = bih1[1 * HID + base] + bhh1[1 * HID + base];
            bg2 = bih1[2 * HID + base] + bhh1[2 * HID + base];
            bg3 = bih1[3 * HID + base] + bhh1[3 * HID + base];
        }
        // each warp waits ONLY on its own source
        const int need = (w < 4) ? quota1(l & 7) : quota2(l & 7);

        for (int t = 0; t < TSEQ; t++) {
            const float* xs;
            const int*   cr;
            if (w < 4) { xs = &g_h1[(size_t)(t + 1) * HP]; cr = &g_c1[(t + 1) * NGRP]; }
            else       { xs = &g_h2[(size_t)t * HP];       cr = &g_c2[t * NGRP]; }

            float x[16];
            acquire_row(xs, cr, l, need, x);

            float* sb = sums[t & 1];
#pragma unroll
            for (int j = 0; j < RPW1; j++) {
                float acc = 0.f;
#pragma unroll
                for (int k = 0; k < 16; k++) acc = fmaf(wreg[j][k], x[k], acc);
#pragma unroll
                for (int off = 16; off; off >>= 1)
                    acc += __shfl_xor_sync(0xffffffffu, acc, off);
                if (l == 0) sb[w * RPW1 + j] = acc;
            }
            __syncthreads();

            if (w == 0) {
                if (l < U1) {
                    float pi = sb[0 * U1 + l] + sb[24 + 0 * U1 + l] + bg0;
                    float pf = sb[1 * U1 + l] + sb[24 + 1 * U1 + l] + bg1;
                    float pg = sb[2 * U1 + l] + sb[24 + 2 * U1 + l] + bg2;
                    float po = sb[3 * U1 + l] + sb[24 + 3 * U1 + l] + bg3;
                    float ig = sigf(pi), fg = sigf(pf), og = sigf(po);
                    float gg = tanhfast(pg);
                    c = fg * c + ig * gg;
                    if ((ub + l) < HID)
                        __stcg(&g_h2[(size_t)(t + 1) * HP + ub + l], og * tanhfast(c));
                }
                __syncwarp();
                if (l == 0) red_release(&g_c2[(t + 1) * NGRP + grp]);
            }
        }
    }
}

// ---------------- final FC ----------------
__global__ void k_fc(const float* __restrict__ fcW,
                     const float* __restrict__ fcb,
                     float* __restrict__ out) {
    int b = blockIdx.x;
    int l = threadIdx.x;
    float acc = 0.f;
    for (int k = l; k < HID; k += 32)
        acc += fcW[b * HID + k] * g_h2[TSEQ * HP + k];
#pragma unroll
    for (int off = 16; off; off >>= 1)
        acc += __shfl_xor_sync(0xffffffffu, acc, off);
    if (l == 0) out[b] = acc + fcb[b];
}

// ---------------- launch ----------------
extern "C" void kernel_launch(void* const* d_in, const int* in_sizes, int n_in,
                              void* d_out, int out_size) {
    const int*   seq  = (const int*)  d_in[0];
    const float* emb  = (const float*)d_in[1];
    const float* Wih0 = (const float*)d_in[2];
    const float* Whh0 = (const float*)d_in[3];
    const float* bih0 = (const float*)d_in[4];
    const float* bhh0 = (const float*)d_in[5];
    const float* Wih1 = (const float*)d_in[6];
    const float* Whh1 = (const float*)d_in[7];
    const float* bih1 = (const float*)d_in[8];
    const float* bhh1 = (const float*)d_in[9];
    const float* fcW  = (const float*)d_in[10];
    const float* fcb  = (const float*)d_in[11];

    k_init<<<148, 256>>>();
    k_transpose<<<(EMB * GATES + 255) / 256, 256>>>(Wih0);
    dim3 gx(16, 256);
    k_xproj<<<gx, 128>>>(seq, emb, bih0, bhh0);
    k_lstm<<<NBLK, THREADS>>>(Whh0, Wih1, Whh1, bih1, bhh1);
    k_fc<<<NCLS, 32>>>(fcW, fcb, (float*)d_out);
}